// round 14
// baseline (speedup 1.0000x reference)
#include <cuda_runtime.h>

#define RSAMP 10
#define NPTS_MAX 2048

__device__ double g_acc_event;
__device__ double g_acc_nonevent;   // already includes *dt factor

__device__ __forceinline__ float fsqrt_approx(float x) {
    float r; asm("sqrt.approx.f32 %0, %1;" : "=f"(r) : "f"(x)); return r;
}
__device__ __forceinline__ float fex2_approx(float x) {
    float r; asm("ex2.approx.f32 %0, %1;" : "=f"(r) : "f"(x)); return r;
}

__global__ void init_acc_kernel() {
    g_acc_event = 0.0;
    g_acc_nonevent = 0.0;
}

__device__ __forceinline__ float block_reduce_sum(float v, float* smem) {
    #pragma unroll
    for (int o = 16; o > 0; o >>= 1) v += __shfl_down_sync(0xffffffffu, v, o);
    const int lane = threadIdx.x & 31;
    const int wid  = threadIdx.x >> 5;
    if (lane == 0) smem[wid] = v;
    __syncthreads();
    const int nw = blockDim.x >> 5;
    v = (threadIdx.x < nw) ? smem[threadIdx.x] : 0.0f;
    if (wid == 0) {
        #pragma unroll
        for (int o = 16; o > 0; o >>= 1) v += __shfl_down_sync(0xffffffffu, v, o);
    }
    return v;
}

// ---------------- events: sum over events of (b - ||dz + dv*t||) ----------------
__global__ void events_kernel(const float* __restrict__ beta,
                              const float* __restrict__ z0,
                              const float* __restrict__ v0,
                              const int*   __restrict__ uv,
                              const float* __restrict__ tev,
                              int n_events)
{
    __shared__ float red[32];
    const float b = __ldg(beta);
    float acc = 0.0f;
    const int stride = gridDim.x * blockDim.x;
    const float2* z2 = (const float2*)z0;
    const float2* v2 = (const float2*)v0;
    for (int e = blockIdx.x * blockDim.x + threadIdx.x; e < n_events; e += stride) {
        const int u = __ldg(&uv[2 * e + 0]);
        const int v = __ldg(&uv[2 * e + 1]);
        const float t = __ldg(&tev[e]);
        const float2 zu = __ldg(&z2[u]);
        const float2 zv = __ldg(&z2[v]);
        const float2 vu = __ldg(&v2[u]);
        const float2 vv = __ldg(&v2[v]);
        const float px = (zu.x - zv.x) + (vu.x - vv.x) * t;
        const float py = (zu.y - zv.y) + (vu.y - vv.y) * t;
        const float d = fsqrt_approx(fmaxf(fmaf(px, px, py * py), 0.0f));
        acc += (b - d);
    }
    acc = block_reduce_sum(acc, red);
    if (threadIdx.x == 0) atomicAdd(&g_acc_event, (double)acc);
}

// ----- pairs: sum over i<j, 10 midpoint samples of exp(b - ||pdz + pdv*t||) * dt -----
// block b handles rows b and (n-1-b): exactly (n-1) pairs per block -> perfect balance.
__global__ __launch_bounds__(256) void pairs_kernel(const float* __restrict__ beta,
                             const float* __restrict__ z0,
                             const float* __restrict__ v0,
                             const float* __restrict__ t0p,
                             const float* __restrict__ tnp,
                             int n)
{
    __shared__ float2 sz[NPTS_MAX];
    __shared__ float2 sv[NPTS_MAX];
    __shared__ float red[32];

    const float2* z2 = (const float2*)z0;
    const float2* v2 = (const float2*)v0;
    for (int i = threadIdx.x; i < n; i += blockDim.x) {
        sz[i] = __ldg(&z2[i]);
        sv[i] = __ldg(&v2[i]);
    }
    __syncthreads();

    const float b  = __ldg(beta);
    const float t0 = __ldg(t0p);
    const float tn = __ldg(tnp);
    const float dt = (tn - t0) * (1.0f / RSAMP);
    const float L2E = 1.4426950408889634f;
    const float bl2 = b * L2E;

    // Hoist Riemann abscissae: t[s] and t[s]^2 are pair-invariant.
    float ts[RSAMP], ts2[RSAMP];
    #pragma unroll
    for (int s = 0; s < RSAMP; s++) {
        ts[s]  = fmaf(((float)s + 0.5f), dt, t0);
        ts2[s] = ts[s] * ts[s];
    }

    float acc = 0.0f;

    #pragma unroll
    for (int rsel = 0; rsel < 2; rsel++) {
        const int i = rsel ? (n - 1 - (int)blockIdx.x) : (int)blockIdx.x;
        const float2 zi = sz[i];
        const float2 vi = sv[i];
        for (int j = i + 1 + (int)threadIdx.x; j < n; j += blockDim.x) {
            const float2 zj = sz[j];
            const float2 vj = sv[j];
            const float dx = zi.x - zj.x;
            const float dy = zi.y - zj.y;
            const float ex = vi.x - vj.x;
            const float ey = vi.y - vj.y;
            // ||dz + dv*t||^2 = qa*t^2 + qb*t + qc
            const float qa = fmaf(ex, ex, ey * ey);
            const float qb = 2.0f * fmaf(dx, ex, dy * ey);
            const float qc = fmaf(dx, dx, dy * dy);
            #pragma unroll
            for (int s = 0; s < RSAMP; s++) {
                // clamp: quadratic can round to tiny negative near its minimum
                const float ss = fmaxf(fmaf(qa, ts2[s], fmaf(qb, ts[s], qc)), 0.0f);
                const float d  = fsqrt_approx(ss);
                acc += fex2_approx(fmaf(-d, L2E, bl2));   // exp(b - d)
            }
        }
    }

    acc = block_reduce_sum(acc, red);
    if (threadIdx.x == 0) atomicAdd(&g_acc_nonevent, (double)acc * (double)dt);
}

__global__ void finalize_kernel(float* __restrict__ out) {
    out[0] = (float)(g_acc_event - g_acc_nonevent);
}

extern "C" void kernel_launch(void* const* d_in, const int* in_sizes, int n_in,
                              void* d_out, int out_size)
{
    const float* beta = (const float*)d_in[0];
    const float* z0   = (const float*)d_in[1];
    const float* v0   = (const float*)d_in[2];
    const int*   uv   = (const int*)  d_in[3];
    const float* tev  = (const float*)d_in[4];
    const float* t0p  = (const float*)d_in[5];
    const float* tnp  = (const float*)d_in[6];
    float* out = (float*)d_out;

    const int n_points = in_sizes[1] / 2;
    const int n_events = in_sizes[4];

    init_acc_kernel<<<1, 1>>>();

    const int eth = 256;
    int eblocks = (n_events + eth - 1) / eth;
    if (eblocks > 1184) eblocks = 1184;   // grid-stride beyond this
    events_kernel<<<eblocks, eth>>>(beta, z0, v0, uv, tev, n_events);

    const int pblocks = n_points / 2;     // rows paired (b, n-1-b)
    pairs_kernel<<<pblocks, 256>>>(beta, z0, v0, t0p, tnp, n_points);

    finalize_kernel<<<1, 1>>>(out);
}

// round 15
// speedup vs baseline: 1.5000x; 1.5000x over previous
#include <cuda_runtime.h>

#define RSAMP 10
#define NPTS_MAX 2048

__device__ double g_acc_event;
__device__ double g_acc_nonevent;   // already includes *dt factor

__device__ __forceinline__ float fsqrt_approx(float x) {
    float r; asm("sqrt.approx.f32 %0, %1;" : "=f"(r) : "f"(x)); return r;
}
__device__ __forceinline__ float fex2_approx(float x) {
    float r; asm("ex2.approx.f32 %0, %1;" : "=f"(r) : "f"(x)); return r;
}

__global__ void init_acc_kernel() {
    g_acc_event = 0.0;
    g_acc_nonevent = 0.0;
}

__device__ __forceinline__ float block_reduce_sum(float v, float* smem) {
    #pragma unroll
    for (int o = 16; o > 0; o >>= 1) v += __shfl_down_sync(0xffffffffu, v, o);
    const int lane = threadIdx.x & 31;
    const int wid  = threadIdx.x >> 5;
    if (lane == 0) smem[wid] = v;
    __syncthreads();
    const int nw = blockDim.x >> 5;
    v = (threadIdx.x < nw) ? smem[threadIdx.x] : 0.0f;
    if (wid == 0) {
        #pragma unroll
        for (int o = 16; o > 0; o >>= 1) v += __shfl_down_sync(0xffffffffu, v, o);
    }
    return v;
}

// ---------------- events: sum over events of (b - ||dz + dv*t||) ----------------
__global__ void events_kernel(const float* __restrict__ beta,
                              const float* __restrict__ z0,
                              const float* __restrict__ v0,
                              const int*   __restrict__ uv,
                              const float* __restrict__ tev,
                              int n_events)
{
    __shared__ float red[32];
    const float b = __ldg(beta);
    float acc = 0.0f;
    const int stride = gridDim.x * blockDim.x;
    const float2* z2 = (const float2*)z0;
    const float2* v2 = (const float2*)v0;
    for (int e = blockIdx.x * blockDim.x + threadIdx.x; e < n_events; e += stride) {
        const int u = __ldg(&uv[2 * e + 0]);
        const int v = __ldg(&uv[2 * e + 1]);
        const float t = __ldg(&tev[e]);
        const float2 zu = __ldg(&z2[u]);
        const float2 zv = __ldg(&z2[v]);
        const float2 vu = __ldg(&v2[u]);
        const float2 vv = __ldg(&v2[v]);
        const float px = (zu.x - zv.x) + (vu.x - vv.x) * t;
        const float py = (zu.y - zv.y) + (vu.y - vv.y) * t;
        const float d = fsqrt_approx(fmaxf(fmaf(px, px, py * py), 0.0f));
        acc += (b - d);
    }
    acc = block_reduce_sum(acc, red);
    if (threadIdx.x == 0) atomicAdd(&g_acc_event, (double)acc);
}

// ----- pairs: sum over i<j, 10 midpoint samples of exp(b - ||pdz + pdv*t||) * dt -----
// block b handles rows b and (n-1-b): exactly (n-1) pairs per block -> perfect balance.
__global__ __launch_bounds__(256) void pairs_kernel(const float* __restrict__ beta,
                             const float* __restrict__ z0,
                             const float* __restrict__ v0,
                             const float* __restrict__ t0p,
                             const float* __restrict__ tnp,
                             int n)
{
    __shared__ float2 sz[NPTS_MAX];
    __shared__ float2 sv[NPTS_MAX];
    __shared__ float red[32];

    const float2* z2 = (const float2*)z0;
    const float2* v2 = (const float2*)v0;
    for (int i = threadIdx.x; i < n; i += blockDim.x) {
        sz[i] = __ldg(&z2[i]);
        sv[i] = __ldg(&v2[i]);
    }
    __syncthreads();

    const float b  = __ldg(beta);
    const float t0 = __ldg(t0p);
    const float tn = __ldg(tnp);
    const float dt = (tn - t0) * (1.0f / RSAMP);
    const float L2E = 1.4426950408889634f;
    const float bl2 = b * L2E;

    // Hoist Riemann abscissae: t[s] and t[s]^2 are pair-invariant.
    float ts[RSAMP], ts2[RSAMP];
    #pragma unroll
    for (int s = 0; s < RSAMP; s++) {
        ts[s]  = fmaf(((float)s + 0.5f), dt, t0);
        ts2[s] = ts[s] * ts[s];
    }

    float acc = 0.0f;

    #pragma unroll
    for (int rsel = 0; rsel < 2; rsel++) {
        const int i = rsel ? (n - 1 - (int)blockIdx.x) : (int)blockIdx.x;
        const float2 zi = sz[i];
        const float2 vi = sv[i];
        for (int j = i + 1 + (int)threadIdx.x; j < n; j += blockDim.x) {
            const float2 zj = sz[j];
            const float2 vj = sv[j];
            const float dx = zi.x - zj.x;
            const float dy = zi.y - zj.y;
            const float ex = vi.x - vj.x;
            const float ey = vi.y - vj.y;
            // ||dz + dv*t||^2 = qa*t^2 + qb*t + qc
            const float qa = fmaf(ex, ex, ey * ey);
            const float qb = 2.0f * fmaf(dx, ex, dy * ey);
            const float qc = fmaf(dx, dx, dy * dy);
            #pragma unroll
            for (int s = 0; s < RSAMP; s++) {
                // clamp: quadratic can round to tiny negative near its minimum
                const float ss = fmaxf(fmaf(qa, ts2[s], fmaf(qb, ts[s], qc)), 0.0f);
                const float d  = fsqrt_approx(ss);
                acc += fex2_approx(fmaf(-d, L2E, bl2));   // exp(b - d)
            }
        }
    }

    acc = block_reduce_sum(acc, red);
    if (threadIdx.x == 0) atomicAdd(&g_acc_nonevent, (double)acc * (double)dt);
}

__global__ void finalize_kernel(float* __restrict__ out) {
    out[0] = (float)(g_acc_event - g_acc_nonevent);
}

extern "C" void kernel_launch(void* const* d_in, const int* in_sizes, int n_in,
                              void* d_out, int out_size)
{
    const float* beta = (const float*)d_in[0];
    const float* z0   = (const float*)d_in[1];
    const float* v0   = (const float*)d_in[2];
    const int*   uv   = (const int*)  d_in[3];
    const float* tev  = (const float*)d_in[4];
    const float* t0p  = (const float*)d_in[5];
    const float* tnp  = (const float*)d_in[6];
    float* out = (float*)d_out;

    const int n_points = in_sizes[1] / 2;
    const int n_events = in_sizes[4];

    init_acc_kernel<<<1, 1>>>();

    const int eth = 256;
    int eblocks = (n_events + eth - 1) / eth;
    if (eblocks > 1184) eblocks = 1184;   // grid-stride beyond this
    events_kernel<<<eblocks, eth>>>(beta, z0, v0, uv, tev, n_events);

    const int pblocks = n_points / 2;     // rows paired (b, n-1-b)
    pairs_kernel<<<pblocks, 256>>>(beta, z0, v0, t0p, tnp, n_points);

    finalize_kernel<<<1, 1>>>(out);
}